// round 6
// baseline (speedup 1.0000x reference)
#include <cuda_runtime.h>
#include <cstdint>

#define BB   4
#define NN   2048
#define MM   2048
#define HH   16
#define DHH  64
#define IDD  1024
#define SCALE 0.125f
#define MAXNEG (-3.402823466e38f)

__device__ float g_Q[BB * NN * IDD];
__device__ float g_K[BB * MM * IDD];
__device__ float g_V[BB * MM * IDD];
__device__ float g_AO[BB * NN * IDD];

// ---------------------------------------------------------------------------
// helpers
// ---------------------------------------------------------------------------
__device__ __forceinline__ uint32_t f2t(float x) {
    uint32_t u;
    asm("cvt.rna.tf32.f32 %0, %1;" : "=r"(u) : "f"(x));
    return u;
}

__device__ __forceinline__ void mma8(float* c,
    uint32_t a0, uint32_t a1, uint32_t a2, uint32_t a3,
    uint32_t b0, uint32_t b1)
{
    asm volatile(
        "mma.sync.aligned.m16n8k8.row.col.f32.tf32.tf32.f32 "
        "{%0,%1,%2,%3}, {%4,%5,%6,%7}, {%8,%9}, {%0,%1,%2,%3};"
        : "+f"(c[0]), "+f"(c[1]), "+f"(c[2]), "+f"(c[3])
        : "r"(a0), "r"(a1), "r"(a2), "r"(a3), "r"(b0), "r"(b1));
}

__device__ __forceinline__ void ldsm4(uint32_t* r, uint32_t saddr) {
    asm volatile("ldmatrix.sync.aligned.m8n8.x4.shared.b16 {%0,%1,%2,%3}, [%4];"
        : "=r"(r[0]), "=r"(r[1]), "=r"(r[2]), "=r"(r[3]) : "r"(saddr));
}

// ---------------------------------------------------------------------------
// TF32 GEMM: C[8192 x 1024] = A[8192 x 1024] @ W[1024 x 1024] (+bias)
// 128x128x32 tile, 256 threads, warp tile 64x32. A frags via ldmatrix.
// ---------------------------------------------------------------------------
#define ASP 36
#define BSP 136

__global__ __launch_bounds__(256) void gemm_tf32(
    const float* __restrict__ A, const float* __restrict__ W,
    const float* __restrict__ bias, float* __restrict__ C)
{
    __shared__ uint32_t As[128 * ASP];
    __shared__ uint32_t Bs[32 * BSP];

    const int tid  = threadIdx.x;
    const int lane = tid & 31;
    const int wid  = tid >> 5;
    const int g    = lane >> 2;
    const int tig  = lane & 3;
    const int wm   = wid & 1;
    const int wn   = wid >> 1;
    const int row0 = blockIdx.y * 128;
    const int col0 = blockIdx.x * 128;

    const int arow = lane & 15;
    const int acol = (lane >> 4) * 4;
    const uint32_t As_base = (uint32_t)__cvta_generic_to_shared(As);

    float acc[4][4][4];
#pragma unroll
    for (int mi = 0; mi < 4; mi++)
#pragma unroll
        for (int ni = 0; ni < 4; ni++)
#pragma unroll
            for (int r = 0; r < 4; r++) acc[mi][ni][r] = 0.f;

    for (int kt = 0; kt < 1024; kt += 32) {
#pragma unroll
        for (int i = 0; i < 4; i++) {
            const int f  = tid + i * 256;
            const int r  = f >> 3;
            const int k4 = f & 7;
            const float4 v = *reinterpret_cast<const float4*>(
                A + (size_t)(row0 + r) * 1024 + kt + k4 * 4);
            *reinterpret_cast<uint4*>(&As[r * ASP + k4 * 4]) =
                make_uint4(f2t(v.x), f2t(v.y), f2t(v.z), f2t(v.w));
        }
#pragma unroll
        for (int i = 0; i < 4; i++) {
            const int f  = tid + i * 256;
            const int k  = f >> 5;
            const int n4 = f & 31;
            const float4 v = *reinterpret_cast<const float4*>(
                W + (size_t)(kt + k) * 1024 + col0 + n4 * 4);
            *reinterpret_cast<uint4*>(&Bs[k * BSP + n4 * 4]) =
                make_uint4(f2t(v.x), f2t(v.y), f2t(v.z), f2t(v.w));
        }
        __syncthreads();

#pragma unroll
        for (int kk = 0; kk < 32; kk += 8) {
            uint32_t af[4][4];
#pragma unroll
            for (int mi = 0; mi < 4; mi++) {
                const int m0 = wm * 64 + mi * 16;
                ldsm4(af[mi], As_base + ((m0 + arow) * ASP + acol + kk) * 4);
            }
#pragma unroll
            for (int ni = 0; ni < 4; ni++) {
                const int n0 = wn * 32 + ni * 8;
                const uint32_t b0 = Bs[(kk + tig)     * BSP + n0 + g];
                const uint32_t b1 = Bs[(kk + tig + 4) * BSP + n0 + g];
#pragma unroll
                for (int mi = 0; mi < 4; mi++)
                    mma8(acc[mi][ni], af[mi][0], af[mi][1], af[mi][2], af[mi][3], b0, b1);
            }
        }
        __syncthreads();
    }

#pragma unroll
    for (int mi = 0; mi < 4; mi++) {
        const int rA = row0 + wm * 64 + mi * 16 + g;
#pragma unroll
        for (int ni = 0; ni < 4; ni++) {
            const int col = col0 + wn * 32 + ni * 8 + 2 * tig;
            float b0v = 0.f, b1v = 0.f;
            if (bias) { b0v = bias[col]; b1v = bias[col + 1]; }
            *reinterpret_cast<float2*>(&C[(size_t)rA * 1024 + col]) =
                make_float2(acc[mi][ni][0] + b0v, acc[mi][ni][1] + b1v);
            *reinterpret_cast<float2*>(&C[(size_t)(rA + 8) * 1024 + col]) =
                make_float2(acc[mi][ni][2] + b0v, acc[mi][ni][3] + b1v);
        }
    }
}

// ---------------------------------------------------------------------------
// TF32 flash attention: CTA = 256 queries x (b,h); 16 warps (512 thr),
// warp owns 16 query rows. 64-key chunks. ldmatrix for Q/K/P fragments.
// ---------------------------------------------------------------------------
#define QSP 68

#define ATT_SMEM_BYTES ((256 * QSP + 64 * QSP + 64 * QSP + 256 * QSP) * 4 + 256)

__global__ __launch_bounds__(512) void attn_tc(
    const float* __restrict__ Q, const float* __restrict__ K,
    const float* __restrict__ V, const int* __restrict__ mask,
    float* __restrict__ AO)
{
    extern __shared__ uint32_t sm[];
    uint32_t* Qs = sm;                   // [256][QSP]
    uint32_t* Ks = Qs + 256 * QSP;       // [64][QSP]
    uint32_t* Vs = Ks + 64 * QSP;        // [64][QSP]
    uint32_t* Ss = Vs + 64 * QSP;        // [256][QSP]
    int*      msk = (int*)(Ss + 256 * QSP);

    const int tid  = threadIdx.x;
    const int lane = tid & 31;
    const int wid  = tid >> 5;            // 0..15
    const int g    = lane >> 2;
    const int tig  = lane & 3;
    const int n0   = blockIdx.x * 256;
    const int h    = blockIdx.y;
    const int b    = blockIdx.z;
    const int q0   = wid * 16;            // warp's query rows

    const int arow = lane & 15;                         // A-type (Q, P)
    const int acol = (lane >> 4) * 4;
    const int krow = (lane & 7) + ((lane >> 4) << 3);   // B-type (K)
    const int kcol = (lane & 8) ? 4 : 0;
    const uint32_t Qs_b = (uint32_t)__cvta_generic_to_shared(Qs);
    const uint32_t Ks_b = (uint32_t)__cvta_generic_to_shared(Ks);
    const uint32_t Ss_b = (uint32_t)__cvta_generic_to_shared(Ss);

    // fill Q (scaled), coalesced: 256 rows x 16 float4 = 4096 slots
#pragma unroll
    for (int i = 0; i < 8; i++) {
        const int f  = tid + i * 512;
        const int r  = f >> 4;
        const int d4 = f & 15;
        const float4 v = *reinterpret_cast<const float4*>(
            Q + ((size_t)b * NN + n0 + r) * IDD + h * 64 + d4 * 4);
        *reinterpret_cast<uint4*>(&Qs[r * QSP + d4 * 4]) =
            make_uint4(f2t(v.x * SCALE), f2t(v.y * SCALE),
                       f2t(v.z * SCALE), f2t(v.w * SCALE));
    }

    float o[8][4];
#pragma unroll
    for (int nf = 0; nf < 8; nf++)
#pragma unroll
        for (int r = 0; r < 4; r++) o[nf][r] = 0.f;
    float mA = MAXNEG, mB = MAXNEG, lA = 0.f, lB = 0.f;

    for (int j0 = 0; j0 < MM; j0 += 64) {
        __syncthreads();   // prev chunk done with Ks/Vs (covers Qs fill on c0)

        // fill K, V chunk: 64 rows x 16 float4 = 1024 slots each
#pragma unroll
        for (int i = 0; i < 2; i++) {
            const int f  = tid + i * 512;
            const int r  = f >> 4;
            const int d4 = f & 15;
            const size_t gb = ((size_t)b * MM + j0 + r) * IDD + h * 64 + d4 * 4;
            const float4 kv = *reinterpret_cast<const float4*>(K + gb);
            *reinterpret_cast<uint4*>(&Ks[r * QSP + d4 * 4]) =
                make_uint4(f2t(kv.x), f2t(kv.y), f2t(kv.z), f2t(kv.w));
            const float4 vv = *reinterpret_cast<const float4*>(V + gb);
            *reinterpret_cast<uint4*>(&Vs[r * QSP + d4 * 4]) =
                make_uint4(f2t(vv.x), f2t(vv.y), f2t(vv.z), f2t(vv.w));
        }
        if (tid < 64) msk[tid] = mask[(size_t)b * MM + j0 + tid];
        __syncthreads();

        // ---- S = Q @ K^T ----
        float s[8][4];
#pragma unroll
        for (int nf = 0; nf < 8; nf++)
#pragma unroll
            for (int r = 0; r < 4; r++) s[nf][r] = 0.f;

#pragma unroll
        for (int ks = 0; ks < 8; ks++) {
            const int d0 = ks * 8;
            uint32_t qa[4];
            ldsm4(qa, Qs_b + ((q0 + arow) * QSP + acol + d0) * 4);
#pragma unroll
            for (int np = 0; np < 4; np++) {
                const int jc = np * 16;
                uint32_t kb[4];
                ldsm4(kb, Ks_b + ((jc + krow) * QSP + kcol + d0) * 4);
                mma8(s[2*np],   qa[0], qa[1], qa[2], qa[3], kb[0], kb[1]);
                mma8(s[2*np+1], qa[0], qa[1], qa[2], qa[3], kb[2], kb[3]);
            }
        }

        // ---- mask + online softmax + P->smem ----
        float cmA = MAXNEG, cmB = MAXNEG;
#pragma unroll
        for (int nf = 0; nf < 8; nf++) {
            const int c0 = nf * 8 + 2 * tig;
            if (!msk[c0])     { s[nf][0] = MAXNEG; s[nf][2] = MAXNEG; }
            if (!msk[c0 + 1]) { s[nf][1] = MAXNEG; s[nf][3] = MAXNEG; }
            cmA = fmaxf(cmA, fmaxf(s[nf][0], s[nf][1]));
            cmB = fmaxf(cmB, fmaxf(s[nf][2], s[nf][3]));
        }
        cmA = fmaxf(cmA, __shfl_xor_sync(0xffffffffu, cmA, 1));
        cmA = fmaxf(cmA, __shfl_xor_sync(0xffffffffu, cmA, 2));
        cmB = fmaxf(cmB, __shfl_xor_sync(0xffffffffu, cmB, 1));
        cmB = fmaxf(cmB, __shfl_xor_sync(0xffffffffu, cmB, 2));

        const float mnA = fmaxf(mA, cmA);
        const float mnB = fmaxf(mB, cmB);
        const float alA = __expf(mA - mnA);
        const float alB = __expf(mB - mnB);
        mA = mnA; mB = mnB;

        float suA = 0.f, suB = 0.f;
#pragma unroll
        for (int nf = 0; nf < 8; nf++) {
            const float p0 = __expf(s[nf][0] - mnA);
            const float p1 = __expf(s[nf][1] - mnA);
            const float p2 = __expf(s[nf][2] - mnB);
            const float p3 = __expf(s[nf][3] - mnB);
            suA += p0 + p1;
            suB += p2 + p3;
            const int c0 = nf * 8 + 2 * tig;
            *reinterpret_cast<uint2*>(&Ss[(q0 + g)     * QSP + c0]) =
                make_uint2(f2t(p0), f2t(p1));
            *reinterpret_cast<uint2*>(&Ss[(q0 + g + 8) * QSP + c0]) =
                make_uint2(f2t(p2), f2t(p3));
        }
        suA += __shfl_xor_sync(0xffffffffu, suA, 1);
        suA += __shfl_xor_sync(0xffffffffu, suA, 2);
        suB += __shfl_xor_sync(0xffffffffu, suB, 1);
        suB += __shfl_xor_sync(0xffffffffu, suB, 2);
        lA = lA * alA + suA;
        lB = lB * alB + suB;

#pragma unroll
        for (int nf = 0; nf < 8; nf++) {
            o[nf][0] *= alA; o[nf][1] *= alA;
            o[nf][2] *= alB; o[nf][3] *= alB;
        }
        __syncwarp();   // P stores visible within warp (rows warp-private)

        // ---- O += P @ V ----
#pragma unroll
        for (int ks = 0; ks < 8; ks++) {
            const int s0 = ks * 8;
            uint32_t pa[4];
            ldsm4(pa, Ss_b + ((q0 + arow) * QSP + acol + s0) * 4);
#pragma unroll
            for (int nf = 0; nf < 8; nf++) {
                const int d0 = nf * 8;
                const uint32_t b0 = Vs[(s0 + tig)     * QSP + d0 + g];
                const uint32_t b1 = Vs[(s0 + tig + 4) * QSP + d0 + g];
                mma8(o[nf], pa[0], pa[1], pa[2], pa[3], b0, b1);
            }
        }
    }

    // normalize + write
    const float liA = 1.f / lA;
    const float liB = 1.f / lB;
#pragma unroll
    for (int nf = 0; nf < 8; nf++) {
        const int col = h * 64 + nf * 8 + 2 * tig;
        const size_t rA = ((size_t)b * NN + n0 + q0 + g)     * IDD + col;
        const size_t rB = ((size_t)b * NN + n0 + q0 + g + 8) * IDD + col;
        *reinterpret_cast<float2*>(&AO[rA]) =
            make_float2(o[nf][0] * liA, o[nf][1] * liA);
        *reinterpret_cast<float2*>(&AO[rB]) =
            make_float2(o[nf][2] * liB, o[nf][3] * liB);
    }
}

// ---------------------------------------------------------------------------
// Launch
// ---------------------------------------------------------------------------
extern "C" void kernel_launch(void* const* d_in, const int* in_sizes, int n_in,
                              void* d_out, int out_size)
{
    const float* x    = (const float*)d_in[0];
    const float* ctx  = (const float*)d_in[1];
    const int*   mask = (const int*)d_in[2];
    const float* Wq   = (const float*)d_in[3];
    const float* Wk   = (const float*)d_in[4];
    const float* Wv   = (const float*)d_in[5];
    const float* Wo   = (const float*)d_in[6];
    const float* bo   = (const float*)d_in[7];
    float* out        = (float*)d_out;

    float *Qp, *Kp, *Vp, *AOp;
    cudaGetSymbolAddress((void**)&Qp,  g_Q);
    cudaGetSymbolAddress((void**)&Kp,  g_K);
    cudaGetSymbolAddress((void**)&Vp,  g_V);
    cudaGetSymbolAddress((void**)&AOp, g_AO);

    cudaFuncSetAttribute(attn_tc,
                         cudaFuncAttributeMaxDynamicSharedMemorySize,
                         ATT_SMEM_BYTES);

    const dim3 gg(1024 / 128, (BB * NN) / 128);   // (8, 64)
    const dim3 bk(256);

    gemm_tf32<<<gg, bk>>>(x,   Wq, nullptr, Qp);
    gemm_tf32<<<gg, bk>>>(ctx, Wk, nullptr, Kp);
    gemm_tf32<<<gg, bk>>>(ctx, Wv, nullptr, Vp);

    attn_tc<<<dim3(NN / 256, HH, BB), 512, ATT_SMEM_BYTES>>>(
        Qp, Kp, Vp, mask, AOp);

    gemm_tf32<<<gg, bk>>>(AOp, Wo, bo, out);
}

// round 7
// speedup vs baseline: 1.1867x; 1.1867x over previous
#include <cuda_runtime.h>
#include <cstdint>

#define BB   4
#define NN   2048
#define MM   2048
#define HH   16
#define DHH  64
#define IDD  1024
#define SCALE 0.125f
#define MAXNEG (-3.402823466e38f)

#define XSZ (BB * NN * IDD)   // 8388608
#define WSZ (IDD * IDD)       // 1048576

// fp32 scratch
__device__ float    g_Q[XSZ];
__device__ float    g_K[XSZ];
__device__ float    g_V[XSZ];
// tf32-bit scratch
__device__ uint32_t g_AO[XSZ];
__device__ uint32_t g_xc[XSZ];
__device__ uint32_t g_cc[XSZ];
__device__ uint32_t g_wq[WSZ];
__device__ uint32_t g_wk[WSZ];
__device__ uint32_t g_wv[WSZ];
__device__ uint32_t g_wo[WSZ];

// ---------------------------------------------------------------------------
// helpers
// ---------------------------------------------------------------------------
__device__ __forceinline__ uint32_t f2t(float x) {
    uint32_t u;
    asm("cvt.rna.tf32.f32 %0, %1;" : "=r"(u) : "f"(x));
    return u;
}

__device__ __forceinline__ void mma8(float* c,
    uint32_t a0, uint32_t a1, uint32_t a2, uint32_t a3,
    uint32_t b0, uint32_t b1)
{
    asm volatile(
        "mma.sync.aligned.m16n8k8.row.col.f32.tf32.tf32.f32 "
        "{%0,%1,%2,%3}, {%4,%5,%6,%7}, {%8,%9}, {%0,%1,%2,%3};"
        : "+f"(c[0]), "+f"(c[1]), "+f"(c[2]), "+f"(c[3])
        : "r"(a0), "r"(a1), "r"(a2), "r"(a3), "r"(b0), "r"(b1));
}

__device__ __forceinline__ void ldsm4(uint32_t* r, uint32_t saddr) {
    asm volatile("ldmatrix.sync.aligned.m8n8.x4.shared.b16 {%0,%1,%2,%3}, [%4];"
        : "=r"(r[0]), "=r"(r[1]), "=r"(r[2]), "=r"(r[3]) : "r"(saddr));
}

__device__ __forceinline__ void cp16(uint32_t dst_smem, const void* src) {
    asm volatile("cp.async.cg.shared.global [%0], [%1], 16;"
        :: "r"(dst_smem), "l"(src));
}

// ---------------------------------------------------------------------------
// elementwise fp32 -> tf32 bits
// ---------------------------------------------------------------------------
__global__ __launch_bounds__(256) void cvt_tf32(
    const float* __restrict__ in, uint32_t* __restrict__ out, int n4)
{
    const int i = blockIdx.x * 256 + threadIdx.x;
    if (i < n4) {
        const float4 v = reinterpret_cast<const float4*>(in)[i];
        reinterpret_cast<uint4*>(out)[i] =
            make_uint4(f2t(v.x), f2t(v.y), f2t(v.z), f2t(v.w));
    }
}

// ---------------------------------------------------------------------------
// TF32 GEMM (pre-converted operands): C[8192x1024] = A @ W (+bias)
// 128x128x32 tile, 256 threads, cp.async double-buffered, no CVTs in loop.
// ---------------------------------------------------------------------------
#define ASP 36
#define BSP 136
#define A_WORDS (128 * ASP)
#define B_WORDS (32 * BSP)
#define GEMM_SMEM_BYTES (2 * (A_WORDS + B_WORDS) * 4)

__global__ __launch_bounds__(256) void gemm_tf32(
    const uint32_t* __restrict__ A, const uint32_t* __restrict__ W,
    const float* __restrict__ bias, float* __restrict__ C)
{
    extern __shared__ uint32_t smg[];
    uint32_t* As = smg;                    // [2][A_WORDS]
    uint32_t* Bs = smg + 2 * A_WORDS;      // [2][B_WORDS]

    const int tid  = threadIdx.x;
    const int lane = tid & 31;
    const int wid  = tid >> 5;
    const int g    = lane >> 2;
    const int tig  = lane & 3;
    const int wm   = wid & 1;
    const int wn   = wid >> 1;
    const int row0 = blockIdx.y * 128;
    const int col0 = blockIdx.x * 128;

    const int arow = lane & 15;
    const int acol = (lane >> 4) * 4;
    const uint32_t As_base = (uint32_t)__cvta_generic_to_shared(As);
    const uint32_t Bs_base = (uint32_t)__cvta_generic_to_shared(Bs);

    // per-thread fill coords
    const int far = tid >> 3;        // A row 0..127 (4 iters stride 32... see below)
    const int fak = (tid & 7) * 4;   // A k-word 0,4..28
    const int fbk = tid >> 5;        // B k row (4 iters stride 8)
    const int fbn = (tid & 31) * 4;  // B n-word

    float acc[4][4][4];
#pragma unroll
    for (int mi = 0; mi < 4; mi++)
#pragma unroll
        for (int ni = 0; ni < 4; ni++)
#pragma unroll
            for (int r = 0; r < 4; r++) acc[mi][ni][r] = 0.f;

    // stage fill: 4 x 16B per thread for A and B each
    auto fill = [&](int s, int kt) {
        const uint32_t ab = As_base + s * A_WORDS * 4;
        const uint32_t bb = Bs_base + s * B_WORDS * 4;
#pragma unroll
        for (int i = 0; i < 4; i++) {
            const int r = far + i * 32;
            cp16(ab + (r * ASP + fak) * 4,
                 A + (size_t)(row0 + r) * 1024 + kt + fak);
        }
#pragma unroll
        for (int i = 0; i < 4; i++) {
            const int k = fbk + i * 8;
            cp16(bb + (k * BSP + fbn) * 4,
                 W + (size_t)(kt + k) * 1024 + col0 + fbn);
        }
        asm volatile("cp.async.commit_group;");
    };

    fill(0, 0);

    for (int t = 0; t < 32; t++) {
        const int cur = t & 1;
        if (t + 1 < 32) {
            fill(cur ^ 1, (t + 1) * 32);
            asm volatile("cp.async.wait_group 1;");
        } else {
            asm volatile("cp.async.wait_group 0;");
        }
        __syncthreads();

        const uint32_t ab = As_base + cur * A_WORDS * 4;
        const uint32_t* Bb = Bs + cur * B_WORDS;

#pragma unroll
        for (int kk = 0; kk < 32; kk += 8) {
            uint32_t af[4][4];
#pragma unroll
            for (int mi = 0; mi < 4; mi++) {
                const int m0 = wm * 64 + mi * 16;
                ldsm4(af[mi], ab + ((m0 + arow) * ASP + acol + kk) * 4);
            }
#pragma unroll
            for (int ni = 0; ni < 4; ni++) {
                const int n0 = wn * 32 + ni * 8;
                const uint32_t b0 = Bb[(kk + tig)     * BSP + n0 + g];
                const uint32_t b1 = Bb[(kk + tig + 4) * BSP + n0 + g];
#pragma unroll
                for (int mi = 0; mi < 4; mi++)
                    mma8(acc[mi][ni], af[mi][0], af[mi][1], af[mi][2], af[mi][3], b0, b1);
            }
        }
        __syncthreads();
    }

#pragma unroll
    for (int mi = 0; mi < 4; mi++) {
        const int rA = row0 + wm * 64 + mi * 16 + g;
#pragma unroll
        for (int ni = 0; ni < 4; ni++) {
            const int col = col0 + wn * 32 + ni * 8 + 2 * tig;
            float b0v = 0.f, b1v = 0.f;
            if (bias) { b0v = bias[col]; b1v = bias[col + 1]; }
            *reinterpret_cast<float2*>(&C[(size_t)rA * 1024 + col]) =
                make_float2(acc[mi][ni][0] + b0v, acc[mi][ni][1] + b1v);
            *reinterpret_cast<float2*>(&C[(size_t)(rA + 8) * 1024 + col]) =
                make_float2(acc[mi][ni][2] + b0v, acc[mi][ni][3] + b1v);
        }
    }
}

// ---------------------------------------------------------------------------
// TF32 flash attention (R5-best config): CTA = 256 queries, 8 warps x 32 rows
// (two m16 tiles). 64-key chunks. Epilogue writes tf32 bits into AO.
// ---------------------------------------------------------------------------
#define QSP 68
#define ATT_SMEM_BYTES ((256 * QSP + 64 * QSP + 64 * QSP + 256 * QSP) * 4 + 256)

__global__ __launch_bounds__(256) void attn_tc(
    const float* __restrict__ Q, const float* __restrict__ K,
    const float* __restrict__ V, const int* __restrict__ mask,
    uint32_t* __restrict__ AO)
{
    extern __shared__ uint32_t sm[];
    uint32_t* Qs = sm;                   // [256][QSP]
    uint32_t* Ks = Qs + 256 * QSP;       // [64][QSP]
    uint32_t* Vs = Ks + 64 * QSP;        // [64][QSP]
    uint32_t* Ss = Vs + 64 * QSP;        // [256][QSP]
    int*      msk = (int*)(Ss + 256 * QSP);

    const int tid  = threadIdx.x;
    const int lane = tid & 31;
    const int wid  = tid >> 5;
    const int g    = lane >> 2;
    const int tig  = lane & 3;
    const int n0   = blockIdx.x * 256;
    const int h    = blockIdx.y;
    const int b    = blockIdx.z;
    const int q0   = wid * 32;

    const int arow = lane & 15;
    const int acol = (lane >> 4) * 4;
    const int krow = (lane & 7) + ((lane >> 4) << 3);
    const int kcol = (lane & 8) ? 4 : 0;
    const uint32_t Qs_b = (uint32_t)__cvta_generic_to_shared(Qs);
    const uint32_t Ks_b = (uint32_t)__cvta_generic_to_shared(Ks);
    const uint32_t Ss_b = (uint32_t)__cvta_generic_to_shared(Ss);

#pragma unroll
    for (int i = 0; i < 16; i++) {
        const int f  = tid + i * 256;
        const int r  = f >> 4;
        const int d4 = f & 15;
        const float4 v = *reinterpret_cast<const float4*>(
            Q + ((size_t)b * NN + n0 + r) * IDD + h * 64 + d4 * 4);
        *reinterpret_cast<uint4*>(&Qs[r * QSP + d4 * 4]) =
            make_uint4(f2t(v.x * SCALE), f2t(v.y * SCALE),
                       f2t(v.z * SCALE), f2t(v.w * SCALE));
    }

    float o[2][8][4];
#pragma unroll
    for (int t = 0; t < 2; t++)
#pragma unroll
        for (int nf = 0; nf < 8; nf++)
#pragma unroll
            for (int r = 0; r < 4; r++) o[t][nf][r] = 0.f;
    float mr[2][2], lr[2][2];
#pragma unroll
    for (int t = 0; t < 2; t++) {
        mr[t][0] = MAXNEG; mr[t][1] = MAXNEG;
        lr[t][0] = 0.f;    lr[t][1] = 0.f;
    }

    for (int j0 = 0; j0 < MM; j0 += 64) {
        __syncthreads();

#pragma unroll
        for (int i = 0; i < 4; i++) {
            const int f  = tid + i * 256;
            const int r  = f >> 4;
            const int d4 = f & 15;
            const size_t gb = ((size_t)b * MM + j0 + r) * IDD + h * 64 + d4 * 4;
            const float4 kv = *reinterpret_cast<const float4*>(K + gb);
            *reinterpret_cast<uint4*>(&Ks[r * QSP + d4 * 4]) =
                make_uint4(f2t(kv.x), f2t(kv.y), f2t(kv.z), f2t(kv.w));
            const float4 vv = *reinterpret_cast<const float4*>(V + gb);
            *reinterpret_cast<uint4*>(&Vs[r * QSP + d4 * 4]) =
                make_uint4(f2t(vv.x), f2t(vv.y), f2t(vv.z), f2t(vv.w));
        }
        if (tid < 64) msk[tid] = mask[(size_t)b * MM + j0 + tid];
        __syncthreads();

        float s[2][8][4];
#pragma unroll
        for (int t = 0; t < 2; t++)
#pragma unroll
            for (int nf = 0; nf < 8; nf++)
#pragma unroll
                for (int r = 0; r < 4; r++) s[t][nf][r] = 0.f;

#pragma unroll
        for (int ks = 0; ks < 8; ks++) {
            const int d0 = ks * 8;
            uint32_t qa[2][4];
            ldsm4(qa[0], Qs_b + ((q0 + arow)      * QSP + acol + d0) * 4);
            ldsm4(qa[1], Qs_b + ((q0 + 16 + arow) * QSP + acol + d0) * 4);
#pragma unroll
            for (int np = 0; np < 4; np++) {
                const int jc = np * 16;
                uint32_t kb[4];
                ldsm4(kb, Ks_b + ((jc + krow) * QSP + kcol + d0) * 4);
                mma8(s[0][2*np],   qa[0][0], qa[0][1], qa[0][2], qa[0][3], kb[0], kb[1]);
                mma8(s[0][2*np+1], qa[0][0], qa[0][1], qa[0][2], qa[0][3], kb[2], kb[3]);
                mma8(s[1][2*np],   qa[1][0], qa[1][1], qa[1][2], qa[1][3], kb[0], kb[1]);
                mma8(s[1][2*np+1], qa[1][0], qa[1][1], qa[1][2], qa[1][3], kb[2], kb[3]);
            }
        }

#pragma unroll
        for (int t = 0; t < 2; t++) {
            float cmA = MAXNEG, cmB = MAXNEG;
#pragma unroll
            for (int nf = 0; nf < 8; nf++) {
                const int c0 = nf * 8 + 2 * tig;
                if (!msk[c0])     { s[t][nf][0] = MAXNEG; s[t][nf][2] = MAXNEG; }
                if (!msk[c0 + 1]) { s[t][nf][1] = MAXNEG; s[t][nf][3] = MAXNEG; }
                cmA = fmaxf(cmA, fmaxf(s[t][nf][0], s[t][nf][1]));
                cmB = fmaxf(cmB, fmaxf(s[t][nf][2], s[t][nf][3]));
            }
            cmA = fmaxf(cmA, __shfl_xor_sync(0xffffffffu, cmA, 1));
            cmA = fmaxf(cmA, __shfl_xor_sync(0xffffffffu, cmA, 2));
            cmB = fmaxf(cmB, __shfl_xor_sync(0xffffffffu, cmB, 1));
            cmB = fmaxf(cmB, __shfl_xor_sync(0xffffffffu, cmB, 2));

            const float mnA = fmaxf(mr[t][0], cmA);
            const float mnB = fmaxf(mr[t][1], cmB);
            const float alA = __expf(mr[t][0] - mnA);
            const float alB = __expf(mr[t][1] - mnB);
            mr[t][0] = mnA; mr[t][1] = mnB;

            float suA = 0.f, suB = 0.f;
            const int rA = q0 + t * 16 + g;
#pragma unroll
            for (int nf = 0; nf < 8; nf++) {
                const float p0 = __expf(s[t][nf][0] - mnA);
                const float p1 = __expf(s[t][nf][1] - mnA);
                const float p2 = __expf(s[t][nf][2] - mnB);
                const float p3 = __expf(s[t][nf][3] - mnB);
                suA += p0 + p1;
                suB += p2 + p3;
                const int c0 = nf * 8 + 2 * tig;
                *reinterpret_cast<uint2*>(&Ss[rA       * QSP + c0]) =
                    make_uint2(f2t(p0), f2t(p1));
                *reinterpret_cast<uint2*>(&Ss[(rA + 8) * QSP + c0]) =
                    make_uint2(f2t(p2), f2t(p3));
            }
            suA += __shfl_xor_sync(0xffffffffu, suA, 1);
            suA += __shfl_xor_sync(0xffffffffu, suA, 2);
            suB += __shfl_xor_sync(0xffffffffu, suB, 1);
            suB += __shfl_xor_sync(0xffffffffu, suB, 2);
            lr[t][0] = lr[t][0] * alA + suA;
            lr[t][1] = lr[t][1] * alB + suB;

#pragma unroll
            for (int nf = 0; nf < 8; nf++) {
                o[t][nf][0] *= alA; o[t][nf][1] *= alA;
                o[t][nf][2] *= alB; o[t][nf][3] *= alB;
            }
        }
        __syncwarp();

#pragma unroll
        for (int ks = 0; ks < 8; ks++) {
            const int s0 = ks * 8;
            uint32_t pa[2][4];
            ldsm4(pa[0], Ss_b + ((q0 + arow)      * QSP + acol + s0) * 4);
            ldsm4(pa[1], Ss_b + ((q0 + 16 + arow) * QSP + acol + s0) * 4);
#pragma unroll
            for (int nf = 0; nf < 8; nf++) {
                const int d0 = nf * 8;
                const uint32_t b0 = Vs[(s0 + tig)     * QSP + d0 + g];
                const uint32_t b1 = Vs[(s0 + tig + 4) * QSP + d0 + g];
                mma8(o[0][nf], pa[0][0], pa[0][1], pa[0][2], pa[0][3], b0, b1);
                mma8(o[1][nf], pa[1][0], pa[1][1], pa[1][2], pa[1][3], b0, b1);
            }
        }
    }

    // normalize + write tf32 bits (identical rounding to previous fill-side cvt)
#pragma unroll
    for (int t = 0; t < 2; t++) {
        const float liA = 1.f / lr[t][0];
        const float liB = 1.f / lr[t][1];
        const int rq = q0 + t * 16 + g;
#pragma unroll
        for (int nf = 0; nf < 8; nf++) {
            const int col = h * 64 + nf * 8 + 2 * tig;
            const size_t rA = ((size_t)b * NN + n0 + rq)     * IDD + col;
            const size_t rB = ((size_t)b * NN + n0 + rq + 8) * IDD + col;
            *reinterpret_cast<uint2*>(&AO[rA]) =
                make_uint2(f2t(o[t][nf][0] * liA), f2t(o[t][nf][1] * liA));
            *reinterpret_cast<uint2*>(&AO[rB]) =
                make_uint2(f2t(o[t][nf][2] * liB), f2t(o[t][nf][3] * liB));
        }
    }
}

// ---------------------------------------------------------------------------
// Launch
// ---------------------------------------------------------------------------
extern "C" void kernel_launch(void* const* d_in, const int* in_sizes, int n_in,
                              void* d_out, int out_size)
{
    const float* x    = (const float*)d_in[0];
    const float* ctx  = (const float*)d_in[1];
    const int*   mask = (const int*)d_in[2];
    const float* Wq   = (const float*)d_in[3];
    const float* Wk   = (const float*)d_in[4];
    const float* Wv   = (const float*)d_in[5];
    const float* Wo   = (const float*)d_in[6];
    const float* bo   = (const float*)d_in[7];
    float* out        = (float*)d_out;

    float *Qp, *Kp, *Vp;
    uint32_t *AOp, *xc, *cc, *wq, *wk, *wv, *wo;
    cudaGetSymbolAddress((void**)&Qp,  g_Q);
    cudaGetSymbolAddress((void**)&Kp,  g_K);
    cudaGetSymbolAddress((void**)&Vp,  g_V);
    cudaGetSymbolAddress((void**)&AOp, g_AO);
    cudaGetSymbolAddress((void**)&xc,  g_xc);
    cudaGetSymbolAddress((void**)&cc,  g_cc);
    cudaGetSymbolAddress((void**)&wq,  g_wq);
    cudaGetSymbolAddress((void**)&wk,  g_wk);
    cudaGetSymbolAddress((void**)&wv,  g_wv);
    cudaGetSymbolAddress((void**)&wo,  g_wo);

    cudaFuncSetAttribute(attn_tc,
                         cudaFuncAttributeMaxDynamicSharedMemorySize,
                         ATT_SMEM_BYTES);
    cudaFuncSetAttribute(gemm_tf32,
                         cudaFuncAttributeMaxDynamicSharedMemorySize,
                         GEMM_SMEM_BYTES);

    // pre-convert inputs to tf32 bits
    cvt_tf32<<<XSZ / 4 / 256, 256>>>(x,   xc, XSZ / 4);
    cvt_tf32<<<XSZ / 4 / 256, 256>>>(ctx, cc, XSZ / 4);
    cvt_tf32<<<WSZ / 4 / 256, 256>>>(Wq,  wq, WSZ / 4);
    cvt_tf32<<<WSZ / 4 / 256, 256>>>(Wk,  wk, WSZ / 4);
    cvt_tf32<<<WSZ / 4 / 256, 256>>>(Wv,  wv, WSZ / 4);
    cvt_tf32<<<WSZ / 4 / 256, 256>>>(Wo,  wo, WSZ / 4);

    const dim3 gg(1024 / 128, (BB * NN) / 128);   // (8, 64)
    const dim3 bk(256);

    gemm_tf32<<<gg, bk, GEMM_SMEM_BYTES>>>(xc, wq, nullptr, Qp);
    gemm_tf32<<<gg, bk, GEMM_SMEM_BYTES>>>(cc, wk, nullptr, Kp);
    gemm_tf32<<<gg, bk, GEMM_SMEM_BYTES>>>(cc, wv, nullptr, Vp);

    attn_tc<<<dim3(NN / 256, HH, BB), 256, ATT_SMEM_BYTES>>>(
        Qp, Kp, Vp, mask, AOp);

    gemm_tf32<<<gg, bk, GEMM_SMEM_BYTES>>>(AOp, wo, bo, out);
}